// round 16
// baseline (speedup 1.0000x reference)
#include <cuda_runtime.h>

#define TPB     64
#define NSTAGE  2
#define XF      (TPB * 13)        // floats per x tile
#define PF      (TPB * 30)        // floats per params tile
#define XF4     (XF / 4)          // 3.25*TPB
#define PF4     (PF / 4)          // 7.5*TPB

// Param columns:
// 0 BW, 1 KMAX, 2 B, 3 D, 4 KMIN, 5 KABS, 6 F, 7 KP1, 8 KP2, 9 KP3,
// 10 FSNC, 11 KE1, 12 KE2, 13 K1, 14 K2, 15 VM0, 16 VMX, 17 KM0, 18 M1,
// 19 M2, 20 M4, 21 KA1, 22 KA2, 23 VI, 24 P2U, 25 IB, 26 KI, 27 M30,
// 28 KD, 29 KSC

__device__ __forceinline__ unsigned smem_u32(const void* p) {
    return (unsigned)__cvta_generic_to_shared(p);
}

__device__ __forceinline__ void cp16(unsigned dst, const void* src) {
    asm volatile("cp.async.cg.shared.global [%0], [%1], 16;\n"
                 :: "r"(dst), "l"(src));
}

__device__ __forceinline__ void cp_commit() {
    asm volatile("cp.async.commit_group;\n" ::: "memory");
}

template <int N>
__device__ __forceinline__ void cp_wait() {
    asm volatile("cp.async.wait_group %0;\n" :: "n"(N) : "memory");
}

__device__ __forceinline__ void compute_dx(
    const float xs[13], const float pv[30],
    float ains, float aCHO, float Dbar, float dx[13])
{
    float BW   = pv[0],  KMAX = pv[1],  B    = pv[2],  D    = pv[3];
    float KMIN = pv[4],  KABS = pv[5],  F    = pv[6],  KP1  = pv[7];
    float KP2  = pv[8],  KP3  = pv[9],  FSNC = pv[10], KE1  = pv[11];
    float KE2  = pv[12], K1   = pv[13], K2   = pv[14], VM0  = pv[15];
    float VMX  = pv[16], KM0  = pv[17], M1   = pv[18], M2   = pv[19];
    float M4   = pv[20], KA1  = pv[21], KA2  = pv[22], VI   = pv[23];
    float P2U  = pv[24], IB   = pv[25], KI   = pv[26], M30  = pv[27];
    float KD   = pv[28], KSC  = pv[29];

    float f_insulin = ains * 6000.0f / BW;
    float qsto = xs[0] + xs[1];

    dx[0] = -KMAX * xs[0] + aCHO * 1000.0f;

    float denom = Dbar + 1e-7f;
    float aa = 2.5f / ((1.0f - B) * denom);
    float cc = 2.5f / (D * denom);
    float kgut_true = KMIN + (KMAX - KMIN) * 0.5f *
        (tanhf(aa * (qsto - B * Dbar)) - tanhf(cc * (qsto - D * Dbar)) + 2.0f);
    float kgut = (Dbar > 0.0f) ? kgut_true : KMAX;

    dx[1] = KMAX * xs[0] - xs[1] * kgut;
    dx[2] = kgut * xs[1] - KABS * xs[2];

    float Rat  = F * KABS * xs[2] / BW;
    float EGPt = KP1 - KP2 * xs[3] - KP3 * xs[8];
    float Et   = (xs[3] > KE2) ? KE1 * (xs[3] - KE2) : 0.0f;
    float d3   = fmaxf(EGPt, 0.0f) + Rat - FSNC - Et - K1 * xs[3] + K2 * xs[4];
    dx[3] = (xs[3] >= 0.0f) ? d3 : 0.0f;

    float Vmt  = VM0 + VMX * xs[6];
    float Uidt = Vmt * xs[4] / (KM0 + xs[4]);
    float d4   = -Uidt + K1 * xs[3] - K2 * xs[4];
    dx[4] = (xs[4] >= 0.0f) ? d4 : 0.0f;

    float d5 = -(M2 + M4) * xs[5] + M1 * xs[9] + KA1 * xs[10] + KA2 * xs[11];
    float It = xs[5] / VI;
    dx[5] = (xs[5] >= 0.0f) ? d5 : 0.0f;

    dx[6] = -P2U * xs[6] + P2U * (It - IB);
    dx[7] = -KI * (xs[7] - It);
    dx[8] = -KI * (xs[8] - xs[7]);

    float d9 = -(M1 + M30) * xs[9] + M2 * xs[5];
    dx[9] = (xs[9] >= 0.0f) ? d9 : 0.0f;

    float d10 = f_insulin - (KA1 + KD) * xs[10];
    dx[10] = (xs[10] >= 0.0f) ? d10 : 0.0f;

    float d11 = KD * xs[10] - KA2 * xs[11];
    dx[11] = (xs[11] >= 0.0f) ? d11 : 0.0f;

    float d12 = -KSC * xs[12] + KSC * xs[3];
    dx[12] = (xs[12] >= 0.0f) ? d12 : 0.0f;
}

__global__ __launch_bounds__(TPB)
void t1d_kernel(const float* __restrict__ x,
                const float* __restrict__ params,
                const float* __restrict__ action_ins,
                const float* __restrict__ action_CHO,
                const float* __restrict__ last_Qsto,
                const float* __restrict__ last_foodtaken,
                float* __restrict__ out,
                int n)
{
    __shared__ float sx[NSTAGE][XF];   // x tiles; reused for output staging
    __shared__ float sp[NSTAGE][PF];   // params tiles (global layout, stride 30)

    const int tid = threadIdx.x;
    const int ntiles = n / TPB;        // full tiles (remainder handled scalar)

    // -------- prologue: prefetch first tile into buf 0 --------
    int tile = blockIdx.x;
    if (tile < ntiles) {
        unsigned sxa = smem_u32(&sx[0][0]);
        unsigned spa = smem_u32(&sp[0][0]);
        const float4* xg = (const float4*)(x + (size_t)tile * XF);
        #pragma unroll
        for (int j = 0; j < 3; j++) cp16(sxa + (j * TPB + tid) * 16, xg + j * TPB + tid);
        if (tid < XF4 - 3 * TPB)     cp16(sxa + (3 * TPB + tid) * 16, xg + 3 * TPB + tid);
        const float4* pg = (const float4*)(params + (size_t)tile * PF);
        #pragma unroll
        for (int j = 0; j < 7; j++) cp16(spa + (j * TPB + tid) * 16, pg + j * TPB + tid);
        if (tid < PF4 - 7 * TPB)    cp16(spa + (7 * TPB + tid) * 16, pg + 7 * TPB + tid);
    }
    cp_commit();

    int buf = 0;
    for (; tile < ntiles; tile += gridDim.x) {
        const int i = tile * TPB + tid;

        // scalar per-env inputs for the CURRENT tile (in flight during wait)
        float ains = action_ins[i];
        float aCHO = action_CHO[i];
        float Dbar = last_Qsto[i] + last_foodtaken[i];

        // -------- prefetch NEXT tile into the other buffer --------
        const int nxt = tile + gridDim.x;
        if (nxt < ntiles) {
            unsigned sxa = smem_u32(&sx[buf ^ 1][0]);
            unsigned spa = smem_u32(&sp[buf ^ 1][0]);
            const float4* xg = (const float4*)(x + (size_t)nxt * XF);
            #pragma unroll
            for (int j = 0; j < 3; j++) cp16(sxa + (j * TPB + tid) * 16, xg + j * TPB + tid);
            if (tid < XF4 - 3 * TPB)     cp16(sxa + (3 * TPB + tid) * 16, xg + 3 * TPB + tid);
            const float4* pg = (const float4*)(params + (size_t)nxt * PF);
            #pragma unroll
            for (int j = 0; j < 7; j++) cp16(spa + (j * TPB + tid) * 16, pg + j * TPB + tid);
            if (tid < PF4 - 7 * TPB)    cp16(spa + (7 * TPB + tid) * 16, pg + 7 * TPB + tid);
            cp_commit();
            cp_wait<1>();   // current tile's group complete (in-order)
        } else {
            cp_wait<0>();   // last tile for this CTA: drain everything
        }
        __syncthreads();

        // -------- gather own row (x stride 13: conflict-free; p stride 30: 2-way) --------
        float xs[13], pv[30];
        #pragma unroll
        for (int k = 0; k < 13; k++) xs[k] = sx[buf][tid * 13 + k];
        #pragma unroll
        for (int k = 0; k < 30; k++) pv[k] = sp[buf][tid * 30 + k];

        float dx[13];
        compute_dx(xs, pv, ains, aCHO, Dbar, dx);

        // write own row back into this buffer's x area (no cross-thread hazard)
        #pragma unroll
        for (int k = 0; k < 13; k++) sx[buf][tid * 13 + k] = dx[k];
        __syncthreads();

        // -------- coalesced float4 stores --------
        const float4* sx4 = (const float4*)&sx[buf][0];
        float4* og = (float4*)(out + (size_t)tile * XF);
        #pragma unroll
        for (int j = 0; j < 3; j++) og[j * TPB + tid] = sx4[j * TPB + tid];
        if (tid < XF4 - 3 * TPB)     og[3 * TPB + tid] = sx4[3 * TPB + tid];

        __syncthreads();   // protect this buffer from the next-next prefetch
        buf ^= 1;
    }

    // -------- remainder envs (n % TPB), scalar path, CTA 0 --------
    const int rbase = ntiles * TPB;
    const int ri = rbase + tid;
    if (blockIdx.x == 0 && ri < n) {
        float xs[13], pv[30];
        const float* xr = x + (size_t)ri * 13;
        #pragma unroll
        for (int k = 0; k < 13; k++) xs[k] = xr[k];
        const float* pp = params + (size_t)ri * 30;
        #pragma unroll
        for (int k = 0; k < 30; k++) pv[k] = pp[k];

        float ains = action_ins[ri];
        float aCHO = action_CHO[ri];
        float Dbar = last_Qsto[ri] + last_foodtaken[ri];

        float dx[13];
        compute_dx(xs, pv, ains, aCHO, Dbar, dx);

        float* o = out + (size_t)ri * 13;
        #pragma unroll
        for (int k = 0; k < 13; k++) o[k] = dx[k];
    }
}

extern "C" void kernel_launch(void* const* d_in, const int* in_sizes, int n_in,
                              void* d_out, int out_size)
{
    const float* x    = (const float*)d_in[0];
    const float* prm  = (const float*)d_in[1];
    const float* ains = (const float*)d_in[2];
    const float* acho = (const float*)d_in[3];
    const float* lq   = (const float*)d_in[4];
    const float* lf   = (const float*)d_in[5];
    float* out = (float*)d_out;

    int n = in_sizes[0] / 13;          // x is (N,13)
    int ntiles = n / TPB;

    int blocks = 148 * 10;             // 10 CTAs/SM @ 22KB smem, persistent
    if (blocks > ntiles) blocks = ntiles > 0 ? ntiles : 1;

    t1d_kernel<<<blocks, TPB>>>(x, prm, ains, acho, lq, lf, out, n);
}